// round 1
// baseline (speedup 1.0000x reference)
#include <cuda_runtime.h>
#include <cstdint>

#define BM 128
#define BK 128
#define DCH 8
#define D_DIM 256
#define K_CODES 1024
#define HW 1024

// Scratch (allocations are forbidden; __device__ globals are the sanctioned path)
__device__ float g_eT[D_DIM * K_CODES];   // codebook transposed [d][k]
__device__ float g_e2[K_CODES];           // ||e_k||^2

// Transpose codebook + compute per-code squared norms.
// Norm computed as sum of individually-rounded squares (matches reference's
// elementwise e**2 followed by sum).
__global__ void vq_prep(const float* __restrict__ emb) {
    const int j = blockIdx.x;      // code index
    const int d = threadIdx.x;     // 0..255
    float v = emb[j * D_DIM + d];
    g_eT[d * K_CODES + j] = v;
    float s = __fmul_rn(v, v);
    #pragma unroll
    for (int o = 16; o > 0; o >>= 1)
        s = __fadd_rn(s, __shfl_down_sync(0xFFFFFFFFu, s, o));
    __shared__ float ws[8];
    if ((d & 31) == 0) ws[d >> 5] = s;
    __syncthreads();
    if (d == 0) {
        float t = ws[0];
        #pragma unroll
        for (int w = 1; w < 8; w++) t = __fadd_rn(t, ws[w]);
        g_e2[j] = t;
    }
}

// Main kernel: each block handles 128 consecutive spatial rows (same batch b,
// consecutive hw), loops over all 1024 codes in 128-wide tiles.
// SGEMM-style 8x8 register micro-tiles, fp32 FFMA throughout.
__global__ void __launch_bounds__(256, 2) vq_main(
    const float* __restrict__ z, const float* __restrict__ emb,
    float* __restrict__ zq, float* __restrict__ idxf, float* __restrict__ loss)
{
    __shared__ float zs[DCH][BM];              // z fragment [d][row]
    __shared__ float es[DCH][BK];              // code fragment [d][code]
    __shared__ float szs[BM];                  // ||z_row||^2
    __shared__ unsigned long long rmin[BM];    // packed (ordered-dist | idx)

    const int tid = threadIdx.x;
    const int tx = tid & 15;                   // code-group 0..15
    const int ty = tid >> 4;                   // row-group  0..15
    const int nbase = blockIdx.x * BM;
    const int b = nbase / HW;
    const int hwbase = nbase % HW;             // 128-aligned, fits in one b
    const float* zb = z + (size_t)b * (D_DIM * HW) + hwbase;

    // Per-row ||z||^2, sequential over d (canonical order), rounded squares.
    if (tid < BM) {
        rmin[tid] = ~0ULL;
        float s = 0.f;
        const float* zp = zb + tid;
        for (int d = 0; d < D_DIM; d++) {
            float v = zp[(size_t)d * HW];
            s = __fadd_rn(s, __fmul_rn(v, v));
        }
        szs[tid] = s;
    }
    __syncthreads();

    float minv[8];
    unsigned minj[8];
    #pragma unroll
    for (int i = 0; i < 8; i++) { minv[i] = 3.402823466e38f; minj[i] = 0u; }

    float szr[8];
    #pragma unroll
    for (int i = 0; i < 8; i++) szr[i] = szs[ty * 8 + i];

    const int ldr = tid >> 5;                  // 0..7  (d within chunk)
    const int ldc = (tid & 31) << 2;           // 0..124 (float4 col)

    for (int kt = 0; kt < K_CODES; kt += BK) {
        float acc[8][8];
        #pragma unroll
        for (int i = 0; i < 8; i++)
            #pragma unroll
            for (int j = 0; j < 8; j++) acc[i][j] = 0.f;

        for (int d0 = 0; d0 < D_DIM; d0 += DCH) {
            __syncthreads();
            // coalesced float4 loads: z rows contiguous in hw, eT contiguous in k
            *(float4*)&zs[ldr][ldc] =
                *(const float4*)&zb[(size_t)(d0 + ldr) * HW + ldc];
            *(float4*)&es[ldr][ldc] =
                *(const float4*)&g_eT[(d0 + ldr) * K_CODES + kt + ldc];
            __syncthreads();
            #pragma unroll
            for (int dd = 0; dd < DCH; dd++) {
                float4 za = *(float4*)&zs[dd][ty * 8];
                float4 zc = *(float4*)&zs[dd][ty * 8 + 4];
                float4 ea = *(float4*)&es[dd][tx * 8];
                float4 ec = *(float4*)&es[dd][tx * 8 + 4];
                float zr[8] = {za.x, za.y, za.z, za.w, zc.x, zc.y, zc.z, zc.w};
                float er[8] = {ea.x, ea.y, ea.z, ea.w, ec.x, ec.y, ec.z, ec.w};
                #pragma unroll
                for (int i = 0; i < 8; i++)
                    #pragma unroll
                    for (int j = 0; j < 8; j++)
                        acc[i][j] = __fmaf_rn(zr[i], er[j], acc[i][j]);
            }
        }

        // running argmin update; strict < + ascending code order gives the
        // reference's first-index tie-break.
        #pragma unroll
        for (int j = 0; j < 8; j++) {
            const int code = kt + tx * 8 + j;
            const float e2v = g_e2[code];
            #pragma unroll
            for (int i = 0; i < 8; i++) {
                float t = __fadd_rn(szr[i], e2v);               // fl(sz + e2)
                float dist = __fmaf_rn(-2.0f, acc[i][j], t);    // fl(t - 2*dot)
                if (dist < minv[i]) { minv[i] = dist; minj[i] = (unsigned)code; }
            }
        }
    }

    // Cross-thread reduce: pack ordered-float dist in high 32 bits, idx low.
    // atomicMin then selects min dist, lowest idx on exact ties.
    #pragma unroll
    for (int i = 0; i < 8; i++) {
        unsigned fb = __float_as_uint(minv[i]);
        fb = (fb & 0x80000000u) ? ~fb : (fb | 0x80000000u);
        unsigned long long p =
            ((unsigned long long)fb << 32) | (unsigned long long)minj[i];
        atomicMin(&rmin[ty * 8 + i], p);
    }
    __syncthreads();

    // Epilogue: 2 threads per row, 128 d's each.
    const int r = tid & 127;
    const int half = tid >> 7;
    const int n = nbase + r;
    const unsigned code = (unsigned)(rmin[r] & 0xFFFFFFFFu);
    if (half == 0) idxf[n] = (float)code;
    const float* erow = emb + (size_t)code * D_DIM;
    float* zqb = zq + (size_t)b * (D_DIM * HW) + hwbase;
    float* lrow = loss + (size_t)n * D_DIM;
    #pragma unroll 4
    for (int s = 0; s < D_DIM / 2; s++) {
        const int d = half * (D_DIM / 2) + s;
        float zv = zb[(size_t)d * HW + r];    // coalesced across threads
        float ev = __ldg(&erow[d]);           // sequential per thread, L1-hot
        zqb[(size_t)d * HW + r] = ev;         // coalesced across threads
        float df = __fadd_rn(ev, -zv);
        lrow[d] = __fmul_rn(df, df);          // per-thread contiguous
    }
}

extern "C" void kernel_launch(void* const* d_in, const int* in_sizes, int n_in,
                              void* d_out, int out_size) {
    const float* z   = (const float*)d_in[0];   // [B, D, H, W] = [32,256,32,32]
    const float* emb = (const float*)d_in[1];   // [K, D] = [1024, 256]
    float* out = (float*)d_out;

    const int n_z = in_sizes[0];                // 8388608
    const int N = n_z / D_DIM;                  // 32768 spatial rows

    float* zq   = out;                          // [B, D, H, W]
    float* idxf = out + n_z;                    // [N] (indices as float)
    float* loss = out + n_z + N;                // [B, H, W, D]

    vq_prep<<<K_CODES, D_DIM>>>(emb);
    vq_main<<<N / BM, 256>>>(z, emb, zq, idxf, loss);
}

// round 2
// speedup vs baseline: 1.0669x; 1.0669x over previous
#include <cuda_runtime.h>
#include <cstdint>

#define BM 128
#define BK 128
#define DCH 16
#define D_DIM 256
#define K_CODES 1024
#define HW 1024
#define NCHUNK (D_DIM / DCH)     // 16
#define NKT (K_CODES / BK)       // 8
#define NST (NKT * NCHUNK)       // 128 pipeline stages

// Scratch (allocations forbidden; __device__ globals are the sanctioned path)
__device__ float g_eT[D_DIM * K_CODES];   // codebook transposed [d][k]
__device__ float g_e2[K_CODES];           // ||e_k||^2

// Transpose codebook + per-code squared norms (rounded squares then sum,
// matching the reference's elementwise e**2 -> sum). Unchanged from R1 (exact).
__global__ void vq_prep(const float* __restrict__ emb) {
    const int j = blockIdx.x;
    const int d = threadIdx.x;
    float v = emb[j * D_DIM + d];
    g_eT[d * K_CODES + j] = v;
    float s = __fmul_rn(v, v);
    #pragma unroll
    for (int o = 16; o > 0; o >>= 1)
        s = __fadd_rn(s, __shfl_down_sync(0xFFFFFFFFu, s, o));
    __shared__ float ws[8];
    if ((d & 31) == 0) ws[d >> 5] = s;
    __syncthreads();
    if (d == 0) {
        float t = ws[0];
        #pragma unroll
        for (int w = 1; w < 8; w++) t = __fadd_rn(t, ws[w]);
        g_e2[j] = t;
    }
}

__device__ __forceinline__ void cp_async16_ca(uint32_t dst, const void* src) {
    asm volatile("cp.async.ca.shared.global [%0], [%1], 16;\n" :: "r"(dst), "l"(src));
}
__device__ __forceinline__ void cp_async16_cg(uint32_t dst, const void* src) {
    asm volatile("cp.async.cg.shared.global [%0], [%1], 16;\n" :: "r"(dst), "l"(src));
}
__device__ __forceinline__ void cp_commit() {
    asm volatile("cp.async.commit_group;\n" ::: "memory");
}
__device__ __forceinline__ void cp_wait0() {
    asm volatile("cp.async.wait_group 0;\n" ::: "memory");
}

// Main kernel: flat 128-stage double-buffered cp.async pipeline.
// Each block: 128 rows x all 1024 codes, 8x8 fp32 register micro-tiles.
__global__ void __launch_bounds__(256, 2) vq_main(
    const float* __restrict__ z, const float* __restrict__ emb,
    float* __restrict__ zq, float* __restrict__ idxf, float* __restrict__ loss)
{
    __shared__ float zs[2][DCH][BM];           // 16 KB
    __shared__ float es[2][DCH][BK];           // 16 KB
    __shared__ float szs[BM];
    __shared__ unsigned long long rmin[BM];

    const int tid = threadIdx.x;
    const int tx = tid & 15;
    const int ty = tid >> 4;
    const int nbase = blockIdx.x * BM;
    const int b = nbase / HW;
    const int hwbase = nbase % HW;
    const float* zb = z + (size_t)b * (D_DIM * HW) + hwbase;

    // loader lane mapping: rows lr and lr+8 of the 16-deep chunk, float4 cols
    const int lr = tid >> 5;                   // 0..7
    const int lc = (tid & 31) << 2;            // 0..124

    const uint32_t zs_smem = (uint32_t)__cvta_generic_to_shared(&zs[0][0][0]);
    const uint32_t es_smem = (uint32_t)__cvta_generic_to_shared(&es[0][0][0]);

    // Issue stage 0 immediately so it overlaps the ||z||^2 pass.
    {
        const int d0 = 0, kt = 0;
        cp_async16_ca(zs_smem + ((0 * DCH + lr) * BM + lc) * 4,
                      &zb[(size_t)(d0 + lr) * HW + lc]);
        cp_async16_ca(zs_smem + ((0 * DCH + lr + 8) * BM + lc) * 4,
                      &zb[(size_t)(d0 + lr + 8) * HW + lc]);
        cp_async16_cg(es_smem + ((0 * DCH + lr) * BK + lc) * 4,
                      &g_eT[(d0 + lr) * K_CODES + kt + lc]);
        cp_async16_cg(es_smem + ((0 * DCH + lr + 8) * BK + lc) * 4,
                      &g_eT[(d0 + lr + 8) * K_CODES + kt + lc]);
        cp_commit();
    }

    // Per-row ||z||^2: sequential over d, rounded squares (exactness-critical).
    if (tid < BM) {
        rmin[tid] = ~0ULL;
        float s = 0.f;
        const float* zp = zb + tid;
        for (int d = 0; d < D_DIM; d++) {
            float v = zp[(size_t)d * HW];
            s = __fadd_rn(s, __fmul_rn(v, v));
        }
        szs[tid] = s;
    }
    __syncthreads();   // szs visible before the first argmin epilogue

    float szr[8];
    #pragma unroll
    for (int i = 0; i < 8; i++) szr[i] = szs[ty * 8 + i];

    float minv[8];
    unsigned minj[8];
    #pragma unroll
    for (int i = 0; i < 8; i++) { minv[i] = 3.402823466e38f; minj[i] = 0u; }

    float acc[8][8];

    for (int s = 0; s < NST; s++) {
        const int buf = s & 1;
        const int chunk = s & (NCHUNK - 1);
        const int kt = (s >> 4) * BK;          // s / NCHUNK * BK

        cp_wait0();          // stage s data arrived (only group s pending)
        __syncthreads();     // all threads done with buf^1's previous contents

        // Issue stage s+1 into the other buffer; overlaps compute of stage s.
        if (s + 1 < NST) {
            const int nb = (s + 1) & 1;
            const int nchunk = (s + 1) & (NCHUNK - 1);
            const int nd0 = nchunk * DCH;
            const int nkt = ((s + 1) >> 4) * BK;
            cp_async16_ca(zs_smem + ((nb * DCH + lr) * BM + lc) * 4,
                          &zb[(size_t)(nd0 + lr) * HW + lc]);
            cp_async16_ca(zs_smem + ((nb * DCH + lr + 8) * BM + lc) * 4,
                          &zb[(size_t)(nd0 + lr + 8) * HW + lc]);
            cp_async16_cg(es_smem + ((nb * DCH + lr) * BK + lc) * 4,
                          &g_eT[(nd0 + lr) * K_CODES + nkt + lc]);
            cp_async16_cg(es_smem + ((nb * DCH + lr + 8) * BK + lc) * 4,
                          &g_eT[(nd0 + lr + 8) * K_CODES + nkt + lc]);
            cp_commit();
        }

        if (chunk == 0) {
            #pragma unroll
            for (int i = 0; i < 8; i++)
                #pragma unroll
                for (int j = 0; j < 8; j++) acc[i][j] = 0.f;
        }

        #pragma unroll
        for (int dd = 0; dd < DCH; dd++) {
            float4 za = *(float4*)&zs[buf][dd][ty * 8];
            float4 zc = *(float4*)&zs[buf][dd][ty * 8 + 4];
            float4 ea = *(float4*)&es[buf][dd][tx * 8];
            float4 ec = *(float4*)&es[buf][dd][tx * 8 + 4];
            float zr[8] = {za.x, za.y, za.z, za.w, zc.x, zc.y, zc.z, zc.w};
            float er[8] = {ea.x, ea.y, ea.z, ea.w, ec.x, ec.y, ec.z, ec.w};
            #pragma unroll
            for (int i = 0; i < 8; i++)
                #pragma unroll
                for (int j = 0; j < 8; j++)
                    acc[i][j] = __fmaf_rn(zr[i], er[j], acc[i][j]);
        }

        if (chunk == NCHUNK - 1) {
            // running argmin; strict < + ascending code order = first-index
            // tie-break, identical to R1 (exactness-critical).
            #pragma unroll
            for (int j = 0; j < 8; j++) {
                const int code = kt + tx * 8 + j;
                const float e2v = g_e2[code];
                #pragma unroll
                for (int i = 0; i < 8; i++) {
                    float t = __fadd_rn(szr[i], e2v);
                    float dist = __fmaf_rn(-2.0f, acc[i][j], t);
                    if (dist < minv[i]) { minv[i] = dist; minj[i] = (unsigned)code; }
                }
            }
        }
    }

    // Cross-thread reduce: packed ordered-float | idx, atomicMin.
    #pragma unroll
    for (int i = 0; i < 8; i++) {
        unsigned fb = __float_as_uint(minv[i]);
        fb = (fb & 0x80000000u) ? ~fb : (fb | 0x80000000u);
        unsigned long long p =
            ((unsigned long long)fb << 32) | (unsigned long long)minj[i];
        atomicMin(&rmin[ty * 8 + i], p);
    }
    __syncthreads();

    // Epilogue: 2 threads per row, 128 d's each.
    const int r = tid & 127;
    const int half = tid >> 7;
    const int n = nbase + r;
    const unsigned code = (unsigned)(rmin[r] & 0xFFFFFFFFu);
    if (half == 0) idxf[n] = (float)code;
    const float* erow = emb + (size_t)code * D_DIM;
    float* zqb = zq + (size_t)b * (D_DIM * HW) + hwbase;
    float* lrow = loss + (size_t)n * D_DIM;
    #pragma unroll 4
    for (int sft = 0; sft < D_DIM / 2; sft++) {
        const int d = half * (D_DIM / 2) + sft;
        float zv = zb[(size_t)d * HW + r];
        float ev = __ldg(&erow[d]);
        zqb[(size_t)d * HW + r] = ev;
        float df = __fadd_rn(ev, -zv);
        lrow[d] = __fmul_rn(df, df);
    }
}

extern "C" void kernel_launch(void* const* d_in, const int* in_sizes, int n_in,
                              void* d_out, int out_size) {
    const float* z   = (const float*)d_in[0];   // [32,256,32,32]
    const float* emb = (const float*)d_in[1];   // [1024,256]
    float* out = (float*)d_out;

    const int n_z = in_sizes[0];                // 8388608
    const int N = n_z / D_DIM;                  // 32768

    float* zq   = out;
    float* idxf = out + n_z;
    float* loss = out + n_z + N;

    vq_prep<<<K_CODES, D_DIM>>>(emb);
    vq_main<<<N / BM, 256>>>(z, emb, zq, idxf, loss);
}